// round 16
// baseline (speedup 1.0000x reference)
#include <cuda_runtime.h>
#include <cuda_bf16.h>
#include <cstdint>
#include <cstddef>

#define N_USERS  50000
#define N_ITEMS  10000
#define N_NODES  100000
#define EMBD     64
#define VIS_DIM  2048
#define TXT_DIM  300
#define H1V      512
#define H1T      256

#define M_PAD    10112          // 158 * 64
#define KP_TXT   320            // 300 padded to 320
#define K2_VIS   (2 * 2048)
#define K2_TXT   (2 * KP_TXT)
#define NNZ_CAP  1700000

// ---------------- device scratch (static, no allocation) ----------------
__device__ float g_H1v[N_ITEMS * H1V];
__device__ float g_H1t[N_ITEMS * H1T];
__device__ float g_Wvd[EMBD * H1V];
__device__ float g_Wtd[EMBD * H1T];
__device__ float g_bvd[EMBD];
__device__ float g_btd[EMBD];
__device__ float g_ego[N_NODES * EMBD];
__device__ float g_cur[N_NODES * EMBD];
__device__ float g_nb [N_NODES * EMBD];
__device__ float g_nb2[N_NODES * EMBD];
__device__ int4  g_pedge[NNZ_CAP];     // packed (row, col, val_bits, 0)
// [hi|lo] split operand buffers
__device__ __nv_bfloat16 g_Av[(size_t)M_PAD * K2_VIS];
__device__ __nv_bfloat16 g_Bv[(size_t)H1V  * K2_VIS];
__device__ __nv_bfloat16 g_At[(size_t)M_PAD * K2_TXT];
__device__ __nv_bfloat16 g_Bt[(size_t)H1T  * K2_TXT];

// ================= PTX helpers (sm_80+ features only) =================
__device__ __forceinline__ uint32_t smem_u32(const void* p) {
    uint32_t a;
    asm("{ .reg .u64 t; cvta.to.shared.u64 t, %1; cvt.u32.u64 %0, t; }" : "=r"(a) : "l"(p));
    return a;
}
__device__ __forceinline__ void cp_async16(uint32_t s, const void* g) {
    asm volatile("cp.async.cg.shared.global [%0], [%1], 16;" :: "r"(s), "l"(g));
}
__device__ __forceinline__ void cp_commit() { asm volatile("cp.async.commit_group;"); }
template<int N> __device__ __forceinline__ void cp_wait() {
    asm volatile("cp.async.wait_group %0;" :: "n"(N));
}
__device__ __forceinline__ void ldm_x4(uint32_t* r, uint32_t addr) {
    asm volatile("ldmatrix.sync.aligned.m8n8.x4.shared.b16 {%0,%1,%2,%3}, [%4];"
                 : "=r"(r[0]), "=r"(r[1]), "=r"(r[2]), "=r"(r[3]) : "r"(addr));
}
__device__ __forceinline__ void mma16816(float* d, const uint32_t* a, uint32_t b0, uint32_t b1) {
    asm volatile("mma.sync.aligned.m16n8k16.row.col.f32.bf16.bf16.f32 "
                 "{%0,%1,%2,%3}, {%4,%5,%6,%7}, {%8,%9}, {%0,%1,%2,%3};"
                 : "+f"(d[0]), "+f"(d[1]), "+f"(d[2]), "+f"(d[3])
                 : "r"(a[0]), "r"(a[1]), "r"(a[2]), "r"(a[3]), "r"(b0), "r"(b1));
}
// smem tile layout (BK=64): [rows][64 bf16] = row*128B, 8x16B chunks, XOR swizzle
__device__ __forceinline__ uint32_t toff64(int r, int c) {
    return (uint32_t)((r << 7) + (((c) ^ (r & 7)) << 4));
}

// ---------------- fused prelude ----------------
__device__ __forceinline__ void split_store(const float* __restrict__ src,
                                            __nv_bfloat16* __restrict__ dst,
                                            int m, int kq, int Kp2, int Ksrc, bool mvalid) {
    float2 v = make_float2(0.f, 0.f);
    if (mvalid && 2 * kq + 1 < Ksrc)
        v = *(const float2*)(src + (size_t)m * Ksrc + 2 * kq);
    __nv_bfloat16 hx = __float2bfloat16(v.x), hy = __float2bfloat16(v.y);
    __nv_bfloat162 hi; hi.x = hx; hi.y = hy;
    __nv_bfloat162 lo;
    lo.x = __float2bfloat16(v.x - __bfloat162float(hx));
    lo.y = __float2bfloat16(v.y - __bfloat162float(hy));
    __nv_bfloat162* d = (__nv_bfloat162*)dst + (size_t)m * (2 * Kp2) + kq;
    d[0]   = hi;
    d[Kp2] = lo;
}

#define CU_AV  ((size_t)M_PAD * 1024)
#define CU_BV  ((size_t)H1V * 1024)
#define CU_AT  ((size_t)M_PAD * (KP_TXT / 2))
#define CU_BT  ((size_t)H1T * (KP_TXT / 2))
#define CU_CVT (CU_AV + CU_BV + CU_AT + CU_BT)
#define CU_PREP ((size_t)EMBD * (H1V + H1T + 1))
#define CU_EGO  ((size_t)N_NODES * 16)
#define CU_Z    ((size_t)N_NODES * 16)
#define PRE_FIX (CU_CVT + CU_PREP + CU_EGO + 2 * CU_Z)

__global__ void prelude(const float* __restrict__ vf, const float* __restrict__ Wv1,
                        const float* __restrict__ tf, const float* __restrict__ Wt1,
                        const float* __restrict__ Wd, const float* __restrict__ bd,
                        const float* __restrict__ Wv2, const float* __restrict__ bv2,
                        const float* __restrict__ Wt2, const float* __restrict__ bt2,
                        const float4* __restrict__ emb, float* __restrict__ out,
                        const int* __restrict__ arow, const int* __restrict__ acol,
                        const float* __restrict__ aval, int nnz) {
    size_t u = (size_t)blockIdx.x * blockDim.x + threadIdx.x;
    if (u < CU_AV) {
        int m = (int)(u >> 10), kq = (int)(u & 1023);
        split_store(vf, g_Av, m, kq, 1024, VIS_DIM, m < N_ITEMS);
        return;
    }
    u -= CU_AV;
    if (u < CU_BV) {
        int m = (int)(u >> 10), kq = (int)(u & 1023);
        split_store(Wv1, g_Bv, m, kq, 1024, VIS_DIM, true);
        return;
    }
    u -= CU_BV;
    if (u < CU_AT) {
        int m = (int)(u / (KP_TXT / 2)), kq = (int)(u % (KP_TXT / 2));
        split_store(tf, g_At, m, kq, KP_TXT / 2, TXT_DIM, m < N_ITEMS);
        return;
    }
    u -= CU_AT;
    if (u < CU_BT) {
        int m = (int)(u / (KP_TXT / 2)), kq = (int)(u % (KP_TXT / 2));
        split_store(Wt1, g_Bt, m, kq, KP_TXT / 2, TXT_DIM, true);
        return;
    }
    u -= CU_BT;
    if (u < CU_PREP) {
        const int COLS = H1V + H1T + 1;
        int n = (int)(u / COLS), c = (int)(u % COLS);
        if (c < H1V) {
            float a = 0.f;
            #pragma unroll 8
            for (int j = 0; j < EMBD; j++) a += Wd[n * EMBD + j] * Wv2[j * H1V + c];
            g_Wvd[n * H1V + c] = a;
        } else if (c < H1V + H1T) {
            int k = c - H1V;
            float a = 0.f;
            #pragma unroll 8
            for (int j = 0; j < EMBD; j++) a += Wd[n * EMBD + j] * Wt2[j * H1T + k];
            g_Wtd[n * H1T + k] = a;
        } else {
            float av = 0.f, at = 0.f;
            for (int j = 0; j < EMBD; j++) {
                av += Wd[n * EMBD + j] * bv2[j];
                at += Wd[n * EMBD + j] * bt2[j];
            }
            g_bvd[n] = av + bd[n];
            g_btd[n] = at + bd[n];
        }
        return;
    }
    u -= CU_PREP;
    if (u < CU_EGO) {
        int r = (int)(u >> 4), c = (int)(u & 15);
        if (r >= N_USERS && r < N_USERS + N_ITEMS) return;  // items come from fuse_items
        float4 v = emb[u];
        ((float4*)g_ego)[u] = v;
        *(float4*)(out + (size_t)r * 192 + c * 4) = v;
        return;
    }
    u -= CU_EGO;
    if (u < CU_Z) {
        ((float4*)g_nb)[u] = make_float4(0.f, 0.f, 0.f, 0.f);
        return;
    }
    u -= CU_Z;
    if (u < CU_Z) {
        ((float4*)g_nb2)[u] = make_float4(0.f, 0.f, 0.f, 0.f);
        return;
    }
    u -= CU_Z;
    if (u < (size_t)nnz) {
        g_pedge[u] = make_int4(arow[u], acol[u], __float_as_int(aval[u]), 0);
    }
}

// ---------------- mma.sync bf16 GEMM (dual problem, [hi|lo] chunk remap) ----------------
#define GSTG 2
#define TILE_A 8192
#define TILE_B2 16384
#define STAGE_B (TILE_A + TILE_B2)
#define GSMEM (GSTG * STAGE_B)

__global__ __launch_bounds__(128, 4)
void gemm_dual(const __nv_bfloat16* __restrict__ Av, const __nv_bfloat16* __restrict__ Bv,
               const float* __restrict__ biasv, float* __restrict__ Cv,
               const __nv_bfloat16* __restrict__ At, const __nv_bfloat16* __restrict__ Bt,
               const float* __restrict__ biast, float* __restrict__ Ct) {
    int z = blockIdx.z;
    if (z == 1 && blockIdx.y >= H1T / 128) return;
    const __nv_bfloat16* A = z ? At : Av;
    const __nv_bfloat16* B = z ? Bt : Bv;
    const float* bias = z ? biast : biasv;
    float* C = z ? Ct : Cv;
    int Ntot = z ? H1T : H1V;
    int GK2  = z ? K2_TXT : K2_VIS;
    int scs  = z ? (KP_TXT / 64) : (2048 / 64);
    int niter = 3 * scs;                         // 15 / 96
    const int M = N_ITEMS;

    extern __shared__ char smem[];
    uint32_t sbase = smem_u32(smem);
    int tid = threadIdx.x;
    int bm = blockIdx.x * 64, bn = blockIdx.y * 128;

    int rbase = tid >> 3, c0 = tid & 7;
    const char* gA[4]; uint32_t oA[4];
    #pragma unroll
    for (int i = 0; i < 4; i++) {
        int r = rbase + i * 16;
        gA[i] = (const char*)(A + (size_t)(bm + r) * GK2) + c0 * 16;
        oA[i] = toff64(r, c0);
    }
    const char* gB[8]; uint32_t oB[8];
    #pragma unroll
    for (int i = 0; i < 8; i++) {
        int r = rbase + i * 16;
        gB[i] = (const char*)(B + (size_t)(bn + r) * GK2) + c0 * 16;
        oB[i] = toff64(r, c0);
    }

    int w = tid >> 5, lane = tid & 31;
    int wm = w & 1, wn = w >> 1;
    int lrow = lane & 15, lchk = lane >> 4;
    float acc[2][8][4];
    #pragma unroll
    for (int i = 0; i < 2; i++)
        #pragma unroll
        for (int j = 0; j < 8; j++)
            #pragma unroll
            for (int q = 0; q < 4; q++) acc[i][j][q] = 0.f;

    #define GOA(c) ((size_t)(((c) >= 2 * scs) ? (c) - 2 * scs : (c)) * 128)
    #define GOB(c) ((size_t)(((c) < scs) ? (c) : (c) - scs) * 128)

    {
        size_t goA = GOA(0), goB = GOB(0);
        #pragma unroll
        for (int i = 0; i < 4; i++) cp_async16(sbase + oA[i], gA[i] + goA);
        #pragma unroll
        for (int i = 0; i < 8; i++) cp_async16(sbase + TILE_A + oB[i], gB[i] + goB);
        cp_commit();
    }

    for (int it = 0; it < niter; it++) {
        cp_wait<0>();
        __syncthreads();
        {
            int pf = it + 1;
            if (pf < niter) {
                uint32_t sb = sbase + (pf & 1) * STAGE_B;
                size_t goA = GOA(pf), goB = GOB(pf);
                #pragma unroll
                for (int i = 0; i < 4; i++) cp_async16(sb + oA[i], gA[i] + goA);
                #pragma unroll
                for (int i = 0; i < 8; i++) cp_async16(sb + TILE_A + oB[i], gB[i] + goB);
            }
            cp_commit();
        }
        uint32_t sA = sbase + (it & 1) * STAGE_B;
        uint32_t sB = sA + TILE_A;
        #pragma unroll
        for (int ks = 0; ks < 4; ks++) {
            uint32_t Ar[2][4], Br[4][4];
            #pragma unroll
            for (int mi = 0; mi < 2; mi++)
                ldm_x4(Ar[mi], sA + toff64(wm * 32 + mi * 16 + lrow, ks * 2 + lchk));
            #pragma unroll
            for (int nj = 0; nj < 4; nj++)
                ldm_x4(Br[nj], sB + toff64(wn * 64 + nj * 16 + lrow, ks * 2 + lchk));
            #pragma unroll
            for (int mi = 0; mi < 2; mi++)
                #pragma unroll
                for (int n = 0; n < 8; n++)
                    mma16816(acc[mi][n], Ar[mi], Br[n >> 1][n & 1], Br[n >> 1][2 + (n & 1)]);
        }
        __syncthreads();
    }
    #undef GOA
    #undef GOB

    int g = lane >> 2, tig = lane & 3;
    #pragma unroll
    for (int mi = 0; mi < 2; mi++) {
        int gm0 = bm + wm * 32 + mi * 16 + g;
        #pragma unroll
        for (int n = 0; n < 8; n++) {
            int gn = bn + wn * 64 + n * 8 + tig * 2;
            float2 bb = *(const float2*)(bias + gn);
            if (gm0 < M) {
                float2 v;
                v.x = fmaxf(acc[mi][n][0] + bb.x, 0.f);
                v.y = fmaxf(acc[mi][n][1] + bb.y, 0.f);
                *(float2*)(C + (size_t)gm0 * Ntot + gn) = v;
            }
            if (gm0 + 8 < M) {
                float2 v;
                v.x = fmaxf(acc[mi][n][2] + bb.x, 0.f);
                v.y = fmaxf(acc[mi][n][3] + bb.y, 0.f);
                *(float2*)(C + (size_t)(gm0 + 8) * Ntot + gn) = v;
            }
        }
    }
}

// ---------------- fused_item = 0.5*(H1v@Wvd^T + bvd + H1t@Wtd^T + btd) ----------------
__global__ __launch_bounds__(256)
void fuse_items(float* __restrict__ out) {
    __shared__ float As[16][68];
    __shared__ float Bs[16][68];
    int bm = blockIdx.x * 64;
    int tid = threadIdx.x;
    int tx = tid & 15, ty = tid >> 4;
    int lrow = tid >> 2, lkq = (tid & 3) << 2;
    float acc[4][4] = {};

    #pragma unroll
    for (int phase = 0; phase < 2; phase++) {
        const float* A = phase ? g_H1t : g_H1v;
        const float* W = phase ? g_Wtd : g_Wvd;
        int K = phase ? H1T : H1V;
        for (int k0 = 0; k0 < K; k0 += 16) {
            int gm = bm + lrow;
            float4 va = make_float4(0.f, 0.f, 0.f, 0.f);
            if (gm < N_ITEMS) va = *(const float4*)(A + (size_t)gm * K + k0 + lkq);
            As[lkq + 0][lrow] = va.x;
            As[lkq + 1][lrow] = va.y;
            As[lkq + 2][lrow] = va.z;
            As[lkq + 3][lrow] = va.w;
            float4 vb = *(const float4*)(W + (size_t)lrow * K + k0 + lkq);
            Bs[lkq + 0][lrow] = vb.x;
            Bs[lkq + 1][lrow] = vb.y;
            Bs[lkq + 2][lrow] = vb.z;
            Bs[lkq + 3][lrow] = vb.w;
            __syncthreads();
            #pragma unroll
            for (int kk = 0; kk < 16; kk++) {
                float4 a = *(const float4*)&As[kk][ty * 4];
                float4 b = *(const float4*)&Bs[kk][tx * 4];
                float am[4] = {a.x, a.y, a.z, a.w};
                float bn4[4] = {b.x, b.y, b.z, b.w};
                #pragma unroll
                for (int i = 0; i < 4; i++)
                    #pragma unroll
                    for (int j = 0; j < 4; j++)
                        acc[i][j] += am[i] * bn4[j];
            }
            __syncthreads();
        }
    }
    #pragma unroll
    for (int i = 0; i < 4; i++) {
        int gm = bm + ty * 4 + i;
        if (gm >= N_ITEMS) continue;
        #pragma unroll
        for (int j = 0; j < 4; j++) {
            int gn = tx * 4 + j;
            float v = 0.5f * (acc[i][j] + g_bvd[gn] + g_btd[gn]);
            g_ego[(size_t)(N_USERS + gm) * 64 + gn] = v;
            out[(size_t)(N_USERS + gm) * 192 + gn] = v;
        }
    }
}

// ---------------- SpMM: nb[row] += val * cur[col], packed edges + float4 atomics ----------------
__global__ void spmm_packed(const float4* __restrict__ cur, float4* __restrict__ nb, int nnz) {
    int idx = blockIdx.x * blockDim.x + threadIdx.x;
    int e = idx >> 4, l = idx & 15;
    if (e >= nnz) return;
    int4 ed = g_pedge[e];                 // one LDG.128 replaces 3 scalar LDGs
    float v = __int_as_float(ed.z);
    float4 x = cur[(size_t)ed.y * 16 + l];
    float4 m = make_float4(v * x.x, v * x.y, v * x.z, v * x.w);
#if __CUDA_ARCH__ >= 900
    atomicAdd(nb + (size_t)ed.x * 16 + l, m);
#else
    float* p = (float*)(nb + (size_t)ed.x * 16 + l);
    atomicAdd(p + 0, m.x);
    atomicAdd(p + 1, m.y);
    atomicAdd(p + 2, m.z);
    atomicAdd(p + 3, m.w);
#endif
}

// ---------------- dense layer: next = leaky_relu([cur|nb] @ Wc^T + bc) ----------------
__global__ __launch_bounds__(256)
void dense_layer(const float* __restrict__ cur, const float* __restrict__ nb,
                 const float* __restrict__ Wc, const float* __restrict__ bc,
                 float* __restrict__ curout, float* __restrict__ out, int outOff) {
    __shared__ float As[16][68];
    __shared__ float Bs[16][68];
    int bm = blockIdx.x * 64;
    int tid = threadIdx.x;
    int tx = tid & 15, ty = tid >> 4;
    int lrow = tid >> 2, lkq = (tid & 3) << 2;
    float acc[4][4] = {};

    #pragma unroll
    for (int phase = 0; phase < 2; phase++) {
        const float* A = phase ? nb : cur;
        int koff = phase ? 64 : 0;
        #pragma unroll
        for (int k0 = 0; k0 < 64; k0 += 16) {
            int gm = bm + lrow;
            float4 va = (gm < N_NODES) ? *(const float4*)(A + (size_t)gm * 64 + k0 + lkq)
                                       : make_float4(0.f, 0.f, 0.f, 0.f);
            As[lkq + 0][lrow] = va.x;
            As[lkq + 1][lrow] = va.y;
            As[lkq + 2][lrow] = va.z;
            As[lkq + 3][lrow] = va.w;
            float4 vb = *(const float4*)(Wc + (size_t)lrow * 128 + koff + k0 + lkq);
            Bs[lkq + 0][lrow] = vb.x;
            Bs[lkq + 1][lrow] = vb.y;
            Bs[lkq + 2][lrow] = vb.z;
            Bs[lkq + 3][lrow] = vb.w;
            __syncthreads();
            #pragma unroll
            for (int kk = 0; kk < 16; kk++) {
                float4 a = *(const float4*)&As[kk][ty * 4];
                float4 b = *(const float4*)&Bs[kk][tx * 4];
                float am[4] = {a.x, a.y, a.z, a.w};
                float bn4[4] = {b.x, b.y, b.z, b.w};
                #pragma unroll
                for (int i = 0; i < 4; i++)
                    #pragma unroll
                    for (int j = 0; j < 4; j++)
                        acc[i][j] += am[i] * bn4[j];
            }
            __syncthreads();
        }
    }
    #pragma unroll
    for (int i = 0; i < 4; i++) {
        int gm = bm + ty * 4 + i;
        if (gm >= N_NODES) continue;
        #pragma unroll
        for (int j = 0; j < 4; j++) {
            int gn = tx * 4 + j;
            float v = acc[i][j] + bc[gn];
            v = v > 0.f ? v : 0.01f * v;
            if (curout) curout[(size_t)gm * 64 + gn] = v;
            out[(size_t)gm * 192 + outOff + gn] = v;
        }
    }
}

// ---------------- launch ----------------
extern "C" void kernel_launch(void* const* d_in, const int* in_sizes, int n_in,
                              void* d_out, int out_size) {
    const int*   adj_row = (const int*)d_in[0];
    const int*   adj_col = (const int*)d_in[1];
    const float* adj_val = (const float*)d_in[2];
    const float* emb     = (const float*)d_in[3];
    const float* vf      = (const float*)d_in[4];
    const float* tf      = (const float*)d_in[5];
    const float* Wv1 = (const float*)d_in[6],  *bv1 = (const float*)d_in[7];
    const float* Wv2 = (const float*)d_in[8],  *bv2 = (const float*)d_in[9];
    const float* Wt1 = (const float*)d_in[10], *bt1 = (const float*)d_in[11];
    const float* Wt2 = (const float*)d_in[12], *bt2 = (const float*)d_in[13];
    const float* Wd  = (const float*)d_in[14], *bd  = (const float*)d_in[15];
    const float* Wc0 = (const float*)d_in[16], *bc0 = (const float*)d_in[17];
    const float* Wc1 = (const float*)d_in[18], *bc1 = (const float*)d_in[19];
    float* out = (float*)d_out;
    int nnz = in_sizes[0];
    if (nnz > NNZ_CAP) nnz = NNZ_CAP;

    float *p_h1v, *p_h1t, *p_ego, *p_cur, *p_nb, *p_nb2;
    __nv_bfloat16 *p_Av, *p_Bv, *p_At, *p_Bt;
    cudaGetSymbolAddress((void**)&p_h1v, g_H1v);
    cudaGetSymbolAddress((void**)&p_h1t, g_H1t);
    cudaGetSymbolAddress((void**)&p_ego, g_ego);
    cudaGetSymbolAddress((void**)&p_cur, g_cur);
    cudaGetSymbolAddress((void**)&p_nb,  g_nb);
    cudaGetSymbolAddress((void**)&p_nb2, g_nb2);
    cudaGetSymbolAddress((void**)&p_Av,  g_Av);
    cudaGetSymbolAddress((void**)&p_Bv,  g_Bv);
    cudaGetSymbolAddress((void**)&p_At,  g_At);
    cudaGetSymbolAddress((void**)&p_Bt,  g_Bt);

    cudaFuncSetAttribute(gemm_dual, cudaFuncAttributeMaxDynamicSharedMemorySize, GSMEM);

    // #1 fused prelude (weight fold + bf16 splits + ego copy + zero fills + edge pack)
    size_t pre_total = PRE_FIX + (size_t)nnz;
    prelude<<<(int)((pre_total + 255) / 256), 256>>>(vf, Wv1, tf, Wt1, Wd, bd, Wv2, bv2,
                                                     Wt2, bt2, (const float4*)emb, out,
                                                     adj_row, adj_col, adj_val, nnz);
    // #2 tensor-core GEMMs
    gemm_dual<<<dim3(M_PAD / 64, H1V / 128, 2), 128, GSMEM>>>(p_Av, p_Bv, bv1, p_h1v,
                                                              p_At, p_Bt, bt1, p_h1t);
    // #3 item fusion
    fuse_items<<<(N_ITEMS + 63) / 64, 256>>>(out);

    int spmm_blocks = (nnz * 16 + 255) / 256;

    // #4 layer-0 SpMM, #5 dense0, #6 layer-1 SpMM, #7 dense1
    spmm_packed<<<spmm_blocks, 256>>>((const float4*)p_ego, (float4*)p_nb, nnz);
    dense_layer<<<(N_NODES + 63) / 64, 256>>>(p_ego, p_nb, Wc0, bc0, p_cur, out, 64);

    spmm_packed<<<spmm_blocks, 256>>>((const float4*)p_cur, (float4*)p_nb2, nnz);
    dense_layer<<<(N_NODES + 63) / 64, 256>>>(p_cur, p_nb2, Wc1, bc1, nullptr, out, 128);
}

// round 17
// speedup vs baseline: 1.0397x; 1.0397x over previous
#include <cuda_runtime.h>
#include <cuda_bf16.h>
#include <cstdint>
#include <cstddef>

#define N_USERS  50000
#define N_ITEMS  10000
#define N_NODES  100000
#define EMBD     64
#define VIS_DIM  2048
#define TXT_DIM  300
#define H1V      512
#define H1T      256

#define M_PAD    10112          // 158 * 64
#define KP_TXT   320            // 300 padded to 320
#define K2_VIS   (2 * 2048)
#define K2_TXT   (2 * KP_TXT)

// ---------------- device scratch (static, no allocation) ----------------
__device__ float g_H1v[N_ITEMS * H1V];
__device__ float g_H1t[N_ITEMS * H1T];
__device__ float g_Wvd[EMBD * H1V];
__device__ float g_Wtd[EMBD * H1T];
__device__ float g_bvd[EMBD];
__device__ float g_btd[EMBD];
__device__ float g_ego[N_NODES * EMBD];
__device__ float g_cur[N_NODES * EMBD];
__device__ float g_nb [N_NODES * EMBD];
__device__ float g_nb2[N_NODES * EMBD];
// [hi|lo] split operand buffers
__device__ __nv_bfloat16 g_Av[(size_t)M_PAD * K2_VIS];
__device__ __nv_bfloat16 g_Bv[(size_t)H1V  * K2_VIS];
__device__ __nv_bfloat16 g_At[(size_t)M_PAD * K2_TXT];
__device__ __nv_bfloat16 g_Bt[(size_t)H1T  * K2_TXT];

// ================= PTX helpers (sm_80+ features only) =================
__device__ __forceinline__ uint32_t smem_u32(const void* p) {
    uint32_t a;
    asm("{ .reg .u64 t; cvta.to.shared.u64 t, %1; cvt.u32.u64 %0, t; }" : "=r"(a) : "l"(p));
    return a;
}
__device__ __forceinline__ void cp_async16(uint32_t s, const void* g) {
    asm volatile("cp.async.cg.shared.global [%0], [%1], 16;" :: "r"(s), "l"(g));
}
__device__ __forceinline__ void cp_commit() { asm volatile("cp.async.commit_group;"); }
template<int N> __device__ __forceinline__ void cp_wait() {
    asm volatile("cp.async.wait_group %0;" :: "n"(N));
}
__device__ __forceinline__ void ldm_x4(uint32_t* r, uint32_t addr) {
    asm volatile("ldmatrix.sync.aligned.m8n8.x4.shared.b16 {%0,%1,%2,%3}, [%4];"
                 : "=r"(r[0]), "=r"(r[1]), "=r"(r[2]), "=r"(r[3]) : "r"(addr));
}
__device__ __forceinline__ void mma16816(float* d, const uint32_t* a, uint32_t b0, uint32_t b1) {
    asm volatile("mma.sync.aligned.m16n8k16.row.col.f32.bf16.bf16.f32 "
                 "{%0,%1,%2,%3}, {%4,%5,%6,%7}, {%8,%9}, {%0,%1,%2,%3};"
                 : "+f"(d[0]), "+f"(d[1]), "+f"(d[2]), "+f"(d[3])
                 : "r"(a[0]), "r"(a[1]), "r"(a[2]), "r"(a[3]), "r"(b0), "r"(b1));
}
// smem tile layout (BK=64): [rows][64 bf16] = row*128B, 8x16B chunks, XOR swizzle
__device__ __forceinline__ uint32_t toff64(int r, int c) {
    return (uint32_t)((r << 7) + (((c) ^ (r & 7)) << 4));
}

// ---------------- fused prelude ----------------
__device__ __forceinline__ void split_store(const float* __restrict__ src,
                                            __nv_bfloat16* __restrict__ dst,
                                            int m, int kq, int Kp2, int Ksrc, bool mvalid) {
    float2 v = make_float2(0.f, 0.f);
    if (mvalid && 2 * kq + 1 < Ksrc)
        v = *(const float2*)(src + (size_t)m * Ksrc + 2 * kq);
    __nv_bfloat16 hx = __float2bfloat16(v.x), hy = __float2bfloat16(v.y);
    __nv_bfloat162 hi; hi.x = hx; hi.y = hy;
    __nv_bfloat162 lo;
    lo.x = __float2bfloat16(v.x - __bfloat162float(hx));
    lo.y = __float2bfloat16(v.y - __bfloat162float(hy));
    __nv_bfloat162* d = (__nv_bfloat162*)dst + (size_t)m * (2 * Kp2) + kq;
    d[0]   = hi;
    d[Kp2] = lo;
}

#define CU_AV  ((size_t)M_PAD * 1024)
#define CU_BV  ((size_t)H1V * 1024)
#define CU_AT  ((size_t)M_PAD * (KP_TXT / 2))
#define CU_BT  ((size_t)H1T * (KP_TXT / 2))
#define CU_CVT (CU_AV + CU_BV + CU_AT + CU_BT)
#define CU_PREP ((size_t)EMBD * (H1V + H1T + 1))
#define CU_EGO  ((size_t)N_NODES * 16)
#define CU_Z    ((size_t)N_NODES * 16)
#define PRE_TOT (CU_CVT + CU_PREP + CU_EGO + 2 * CU_Z)

__global__ void prelude(const float* __restrict__ vf, const float* __restrict__ Wv1,
                        const float* __restrict__ tf, const float* __restrict__ Wt1,
                        const float* __restrict__ Wd, const float* __restrict__ bd,
                        const float* __restrict__ Wv2, const float* __restrict__ bv2,
                        const float* __restrict__ Wt2, const float* __restrict__ bt2,
                        const float4* __restrict__ emb, float* __restrict__ out) {
    size_t u = (size_t)blockIdx.x * blockDim.x + threadIdx.x;
    if (u < CU_AV) {
        int m = (int)(u >> 10), kq = (int)(u & 1023);
        split_store(vf, g_Av, m, kq, 1024, VIS_DIM, m < N_ITEMS);
        return;
    }
    u -= CU_AV;
    if (u < CU_BV) {
        int m = (int)(u >> 10), kq = (int)(u & 1023);
        split_store(Wv1, g_Bv, m, kq, 1024, VIS_DIM, true);
        return;
    }
    u -= CU_BV;
    if (u < CU_AT) {
        int m = (int)(u / (KP_TXT / 2)), kq = (int)(u % (KP_TXT / 2));
        split_store(tf, g_At, m, kq, KP_TXT / 2, TXT_DIM, m < N_ITEMS);
        return;
    }
    u -= CU_AT;
    if (u < CU_BT) {
        int m = (int)(u / (KP_TXT / 2)), kq = (int)(u % (KP_TXT / 2));
        split_store(Wt1, g_Bt, m, kq, KP_TXT / 2, TXT_DIM, true);
        return;
    }
    u -= CU_BT;
    if (u < CU_PREP) {
        const int COLS = H1V + H1T + 1;
        int n = (int)(u / COLS), c = (int)(u % COLS);
        if (c < H1V) {
            float a = 0.f;
            #pragma unroll 8
            for (int j = 0; j < EMBD; j++) a += Wd[n * EMBD + j] * Wv2[j * H1V + c];
            g_Wvd[n * H1V + c] = a;
        } else if (c < H1V + H1T) {
            int k = c - H1V;
            float a = 0.f;
            #pragma unroll 8
            for (int j = 0; j < EMBD; j++) a += Wd[n * EMBD + j] * Wt2[j * H1T + k];
            g_Wtd[n * H1T + k] = a;
        } else {
            float av = 0.f, at = 0.f;
            for (int j = 0; j < EMBD; j++) {
                av += Wd[n * EMBD + j] * bv2[j];
                at += Wd[n * EMBD + j] * bt2[j];
            }
            g_bvd[n] = av + bd[n];
            g_btd[n] = at + bd[n];
        }
        return;
    }
    u -= CU_PREP;
    if (u < CU_EGO) {
        int r = (int)(u >> 4), c = (int)(u & 15);
        if (r >= N_USERS && r < N_USERS + N_ITEMS) return;  // items come from fuse_items
        float4 v = emb[u];
        ((float4*)g_ego)[u] = v;
        *(float4*)(out + (size_t)r * 192 + c * 4) = v;
        return;
    }
    u -= CU_EGO;
    if (u < CU_Z) {
        ((float4*)g_nb)[u] = make_float4(0.f, 0.f, 0.f, 0.f);
        return;
    }
    u -= CU_Z;
    if (u < CU_Z) {
        ((float4*)g_nb2)[u] = make_float4(0.f, 0.f, 0.f, 0.f);
    }
}

// ---------------- mma.sync bf16 GEMM (dual problem, [hi|lo] chunk remap) ----------------
#define GSTG 2
#define TILE_A 8192
#define TILE_B2 16384
#define STAGE_B (TILE_A + TILE_B2)
#define GSMEM (GSTG * STAGE_B)

__global__ __launch_bounds__(128, 4)
void gemm_dual(const __nv_bfloat16* __restrict__ Av, const __nv_bfloat16* __restrict__ Bv,
               const float* __restrict__ biasv, float* __restrict__ Cv,
               const __nv_bfloat16* __restrict__ At, const __nv_bfloat16* __restrict__ Bt,
               const float* __restrict__ biast, float* __restrict__ Ct) {
    int z = blockIdx.z;
    if (z == 1 && blockIdx.y >= H1T / 128) return;
    const __nv_bfloat16* A = z ? At : Av;
    const __nv_bfloat16* B = z ? Bt : Bv;
    const float* bias = z ? biast : biasv;
    float* C = z ? Ct : Cv;
    int Ntot = z ? H1T : H1V;
    int GK2  = z ? K2_TXT : K2_VIS;
    int scs  = z ? (KP_TXT / 64) : (2048 / 64);
    int niter = 3 * scs;                         // 15 / 96
    const int M = N_ITEMS;

    extern __shared__ char smem[];
    uint32_t sbase = smem_u32(smem);
    int tid = threadIdx.x;
    int bm = blockIdx.x * 64, bn = blockIdx.y * 128;

    int rbase = tid >> 3, c0 = tid & 7;
    const char* gA[4]; uint32_t oA[4];
    #pragma unroll
    for (int i = 0; i < 4; i++) {
        int r = rbase + i * 16;
        gA[i] = (const char*)(A + (size_t)(bm + r) * GK2) + c0 * 16;
        oA[i] = toff64(r, c0);
    }
    const char* gB[8]; uint32_t oB[8];
    #pragma unroll
    for (int i = 0; i < 8; i++) {
        int r = rbase + i * 16;
        gB[i] = (const char*)(B + (size_t)(bn + r) * GK2) + c0 * 16;
        oB[i] = toff64(r, c0);
    }

    int w = tid >> 5, lane = tid & 31;
    int wm = w & 1, wn = w >> 1;
    int lrow = lane & 15, lchk = lane >> 4;
    float acc[2][8][4];
    #pragma unroll
    for (int i = 0; i < 2; i++)
        #pragma unroll
        for (int j = 0; j < 8; j++)
            #pragma unroll
            for (int q = 0; q < 4; q++) acc[i][j][q] = 0.f;

    #define GOA(c) ((size_t)(((c) >= 2 * scs) ? (c) - 2 * scs : (c)) * 128)
    #define GOB(c) ((size_t)(((c) < scs) ? (c) : (c) - scs) * 128)

    {
        size_t goA = GOA(0), goB = GOB(0);
        #pragma unroll
        for (int i = 0; i < 4; i++) cp_async16(sbase + oA[i], gA[i] + goA);
        #pragma unroll
        for (int i = 0; i < 8; i++) cp_async16(sbase + TILE_A + oB[i], gB[i] + goB);
        cp_commit();
    }

    for (int it = 0; it < niter; it++) {
        cp_wait<0>();
        __syncthreads();
        {
            int pf = it + 1;
            if (pf < niter) {
                uint32_t sb = sbase + (pf & 1) * STAGE_B;
                size_t goA = GOA(pf), goB = GOB(pf);
                #pragma unroll
                for (int i = 0; i < 4; i++) cp_async16(sb + oA[i], gA[i] + goA);
                #pragma unroll
                for (int i = 0; i < 8; i++) cp_async16(sb + TILE_A + oB[i], gB[i] + goB);
            }
            cp_commit();
        }
        uint32_t sA = sbase + (it & 1) * STAGE_B;
        uint32_t sB = sA + TILE_A;
        #pragma unroll
        for (int ks = 0; ks < 4; ks++) {
            uint32_t Ar[2][4], Br[4][4];
            #pragma unroll
            for (int mi = 0; mi < 2; mi++)
                ldm_x4(Ar[mi], sA + toff64(wm * 32 + mi * 16 + lrow, ks * 2 + lchk));
            #pragma unroll
            for (int nj = 0; nj < 4; nj++)
                ldm_x4(Br[nj], sB + toff64(wn * 64 + nj * 16 + lrow, ks * 2 + lchk));
            #pragma unroll
            for (int mi = 0; mi < 2; mi++)
                #pragma unroll
                for (int n = 0; n < 8; n++)
                    mma16816(acc[mi][n], Ar[mi], Br[n >> 1][n & 1], Br[n >> 1][2 + (n & 1)]);
        }
        __syncthreads();
    }
    #undef GOA
    #undef GOB

    int g = lane >> 2, tig = lane & 3;
    #pragma unroll
    for (int mi = 0; mi < 2; mi++) {
        int gm0 = bm + wm * 32 + mi * 16 + g;
        #pragma unroll
        for (int n = 0; n < 8; n++) {
            int gn = bn + wn * 64 + n * 8 + tig * 2;
            float2 bb = *(const float2*)(bias + gn);
            if (gm0 < M) {
                float2 v;
                v.x = fmaxf(acc[mi][n][0] + bb.x, 0.f);
                v.y = fmaxf(acc[mi][n][1] + bb.y, 0.f);
                *(float2*)(C + (size_t)gm0 * Ntot + gn) = v;
            }
            if (gm0 + 8 < M) {
                float2 v;
                v.x = fmaxf(acc[mi][n][2] + bb.x, 0.f);
                v.y = fmaxf(acc[mi][n][3] + bb.y, 0.f);
                *(float2*)(C + (size_t)(gm0 + 8) * Ntot + gn) = v;
            }
        }
    }
}

// ---------------- fused_item = 0.5*(H1v@Wvd^T + bvd + H1t@Wtd^T + btd) ----------------
__global__ __launch_bounds__(256)
void fuse_items(float* __restrict__ out) {
    __shared__ float As[16][68];
    __shared__ float Bs[16][68];
    int bm = blockIdx.x * 64;
    int tid = threadIdx.x;
    int tx = tid & 15, ty = tid >> 4;
    int lrow = tid >> 2, lkq = (tid & 3) << 2;
    float acc[4][4] = {};

    #pragma unroll
    for (int phase = 0; phase < 2; phase++) {
        const float* A = phase ? g_H1t : g_H1v;
        const float* W = phase ? g_Wtd : g_Wvd;
        int K = phase ? H1T : H1V;
        for (int k0 = 0; k0 < K; k0 += 16) {
            int gm = bm + lrow;
            float4 va = make_float4(0.f, 0.f, 0.f, 0.f);
            if (gm < N_ITEMS) va = *(const float4*)(A + (size_t)gm * K + k0 + lkq);
            As[lkq + 0][lrow] = va.x;
            As[lkq + 1][lrow] = va.y;
            As[lkq + 2][lrow] = va.z;
            As[lkq + 3][lrow] = va.w;
            float4 vb = *(const float4*)(W + (size_t)lrow * K + k0 + lkq);
            Bs[lkq + 0][lrow] = vb.x;
            Bs[lkq + 1][lrow] = vb.y;
            Bs[lkq + 2][lrow] = vb.z;
            Bs[lkq + 3][lrow] = vb.w;
            __syncthreads();
            #pragma unroll
            for (int kk = 0; kk < 16; kk++) {
                float4 a = *(const float4*)&As[kk][ty * 4];
                float4 b = *(const float4*)&Bs[kk][tx * 4];
                float am[4] = {a.x, a.y, a.z, a.w};
                float bn4[4] = {b.x, b.y, b.z, b.w};
                #pragma unroll
                for (int i = 0; i < 4; i++)
                    #pragma unroll
                    for (int j = 0; j < 4; j++)
                        acc[i][j] += am[i] * bn4[j];
            }
            __syncthreads();
        }
    }
    #pragma unroll
    for (int i = 0; i < 4; i++) {
        int gm = bm + ty * 4 + i;
        if (gm >= N_ITEMS) continue;
        #pragma unroll
        for (int j = 0; j < 4; j++) {
            int gn = tx * 4 + j;
            float v = 0.5f * (acc[i][j] + g_bvd[gn] + g_btd[gn]);
            g_ego[(size_t)(N_USERS + gm) * 64 + gn] = v;
            out[(size_t)(N_USERS + gm) * 192 + gn] = v;
        }
    }
}

// ---------------- SpMM: nb[row] += val * cur[col], float4 atomics (structural floor) --------
__global__ void spmm_atomic(const int* __restrict__ arow, const int* __restrict__ acol,
                            const float* __restrict__ aval, const float4* __restrict__ cur,
                            float4* __restrict__ nb, int nnz) {
    int idx = blockIdx.x * blockDim.x + threadIdx.x;
    int e = idx >> 4, l = idx & 15;
    if (e >= nnz) return;
    int r = arow[e];
    int c = acol[e];
    float v = aval[e];
    float4 x = cur[(size_t)c * 16 + l];
    float4 m = make_float4(v * x.x, v * x.y, v * x.z, v * x.w);
#if __CUDA_ARCH__ >= 900
    atomicAdd(nb + (size_t)r * 16 + l, m);
#else
    float* p = (float*)(nb + (size_t)r * 16 + l);
    atomicAdd(p + 0, m.x);
    atomicAdd(p + 1, m.y);
    atomicAdd(p + 2, m.z);
    atomicAdd(p + 3, m.w);
#endif
}

// ---------------- dense layer: next = leaky_relu([cur|nb] @ Wc^T + bc) ----------------
// BM=128 (TM=8), BN=64, K=128 across two phases; 256 threads.
__global__ __launch_bounds__(256)
void dense_layer(const float* __restrict__ cur, const float* __restrict__ nb,
                 const float* __restrict__ Wc, const float* __restrict__ bc,
                 float* __restrict__ curout, float* __restrict__ out, int outOff) {
    __shared__ float As[16][132];
    __shared__ float Bs[16][68];
    int bm = blockIdx.x * 128;
    int tid = threadIdx.x;
    int tx = tid & 15, ty = tid >> 4;
    float acc[8][4] = {};

    #pragma unroll
    for (int phase = 0; phase < 2; phase++) {
        const float* A = phase ? nb : cur;
        int koff = phase ? 64 : 0;
        #pragma unroll
        for (int k0 = 0; k0 < 64; k0 += 16) {
            // A tile 128x16: 2 x float4 per thread
            #pragma unroll
            for (int rr = 0; rr < 2; rr++) {
                int idx = tid + rr * 256;
                int row = idx >> 2;            // 0..127
                int kq  = (idx & 3) << 2;
                int gm = bm + row;
                float4 va = (gm < N_NODES) ? *(const float4*)(A + (size_t)gm * 64 + k0 + kq)
                                           : make_float4(0.f, 0.f, 0.f, 0.f);
                As[kq + 0][row] = va.x;
                As[kq + 1][row] = va.y;
                As[kq + 2][row] = va.z;
                As[kq + 3][row] = va.w;
            }
            // B tile 16x64: 1 x float4 per thread
            {
                int n  = tid >> 2;             // 0..63
                int kq = (tid & 3) << 2;
                float4 vb = *(const float4*)(Wc + (size_t)n * 128 + koff + k0 + kq);
                Bs[kq + 0][n] = vb.x;
                Bs[kq + 1][n] = vb.y;
                Bs[kq + 2][n] = vb.z;
                Bs[kq + 3][n] = vb.w;
            }
            __syncthreads();
            #pragma unroll
            for (int kk = 0; kk < 16; kk++) {
                float4 a0 = *(const float4*)&As[kk][ty * 8];
                float4 a1 = *(const float4*)&As[kk][ty * 8 + 4];
                float4 b  = *(const float4*)&Bs[kk][tx * 4];
                float am[8] = {a0.x, a0.y, a0.z, a0.w, a1.x, a1.y, a1.z, a1.w};
                float bn4[4] = {b.x, b.y, b.z, b.w};
                #pragma unroll
                for (int i = 0; i < 8; i++)
                    #pragma unroll
                    for (int j = 0; j < 4; j++)
                        acc[i][j] += am[i] * bn4[j];
            }
            __syncthreads();
        }
    }
    #pragma unroll
    for (int i = 0; i < 8; i++) {
        int gm = bm + ty * 8 + i;
        if (gm >= N_NODES) continue;
        #pragma unroll
        for (int j = 0; j < 4; j++) {
            int gn = tx * 4 + j;
            float v = acc[i][j] + bc[gn];
            v = v > 0.f ? v : 0.01f * v;
            if (curout) curout[(size_t)gm * 64 + gn] = v;
            out[(size_t)gm * 192 + outOff + gn] = v;
        }
    }
}

// ---------------- launch ----------------
extern "C" void kernel_launch(void* const* d_in, const int* in_sizes, int n_in,
                              void* d_out, int out_size) {
    const int*   adj_row = (const int*)d_in[0];
    const int*   adj_col = (const int*)d_in[1];
    const float* adj_val = (const float*)d_in[2];
    const float* emb     = (const float*)d_in[3];
    const float* vf      = (const float*)d_in[4];
    const float* tf      = (const float*)d_in[5];
    const float* Wv1 = (const float*)d_in[6],  *bv1 = (const float*)d_in[7];
    const float* Wv2 = (const float*)d_in[8],  *bv2 = (const float*)d_in[9];
    const float* Wt1 = (const float*)d_in[10], *bt1 = (const float*)d_in[11];
    const float* Wt2 = (const float*)d_in[12], *bt2 = (const float*)d_in[13];
    const float* Wd  = (const float*)d_in[14], *bd  = (const float*)d_in[15];
    const float* Wc0 = (const float*)d_in[16], *bc0 = (const float*)d_in[17];
    const float* Wc1 = (const float*)d_in[18], *bc1 = (const float*)d_in[19];
    float* out = (float*)d_out;
    int nnz = in_sizes[0];

    float *p_h1v, *p_h1t, *p_ego, *p_cur, *p_nb, *p_nb2;
    __nv_bfloat16 *p_Av, *p_Bv, *p_At, *p_Bt;
    cudaGetSymbolAddress((void**)&p_h1v, g_H1v);
    cudaGetSymbolAddress((void**)&p_h1t, g_H1t);
    cudaGetSymbolAddress((void**)&p_ego, g_ego);
    cudaGetSymbolAddress((void**)&p_cur, g_cur);
    cudaGetSymbolAddress((void**)&p_nb,  g_nb);
    cudaGetSymbolAddress((void**)&p_nb2, g_nb2);
    cudaGetSymbolAddress((void**)&p_Av,  g_Av);
    cudaGetSymbolAddress((void**)&p_Bv,  g_Bv);
    cudaGetSymbolAddress((void**)&p_At,  g_At);
    cudaGetSymbolAddress((void**)&p_Bt,  g_Bt);

    cudaFuncSetAttribute(gemm_dual, cudaFuncAttributeMaxDynamicSharedMemorySize, GSMEM);

    // #1 fused prelude (weight fold + bf16 splits + ego copy + both zero fills)
    prelude<<<(int)((PRE_TOT + 255) / 256), 256>>>(vf, Wv1, tf, Wt1, Wd, bd, Wv2, bv2,
                                                   Wt2, bt2, (const float4*)emb, out);
    // #2 tensor-core GEMMs
    gemm_dual<<<dim3(M_PAD / 64, H1V / 128, 2), 128, GSMEM>>>(p_Av, p_Bv, bv1, p_h1v,
                                                              p_At, p_Bt, bt1, p_h1t);
    // #3 item fusion
    fuse_items<<<(N_ITEMS + 63) / 64, 256>>>(out);

    int spmm_blocks = (nnz * 16 + 255) / 256;

    // #4 layer-0 SpMM, #5 dense0, #6 layer-1 SpMM, #7 dense1
    spmm_atomic<<<spmm_blocks, 256>>>(adj_row, adj_col, adj_val,
                                      (const float4*)p_ego, (float4*)p_nb, nnz);
    dense_layer<<<(N_NODES + 127) / 128, 256>>>(p_ego, p_nb, Wc0, bc0, p_cur, out, 64);

    spmm_atomic<<<spmm_blocks, 256>>>(adj_row, adj_col, adj_val,
                                      (const float4*)p_cur, (float4*)p_nb2, nnz);
    dense_layer<<<(N_NODES + 127) / 128, 256>>>(p_cur, p_nb2, Wc1, bc1, nullptr, out, 128);
}